// round 11
// baseline (speedup 1.0000x reference)
#include <cuda_runtime.h>
#include <math.h>

// ---------------- problem constants ----------------
#define NL     8          // layers
#define NB     8          // batch
#define NCH    64         // channels
#define HH     96
#define WW     96
#define PLANE  (HH*WW)            // 9216
#define IMG    (NCH*PLANE)        // 589824
#define SS     (NB*IMG)           // 4718592  (one layer-slot: [B,C,H,W])
#define S4     (SS/4)             // 1179648
#define NTILES 72                 // (96/16) * (96/8)
#define CB     8                  // cin chunk

// ---------------- scratch (device globals; no mallocs allowed) ----------------
__device__ float g_Z [NL*SS];     // ~151 MB
__device__ float g_dZ[NL*SS];     // ~151 MB
__device__ float g_Y [NL*SS];     // ~151 MB
__device__ float g_sbuf[NL*NB*NCH*NTILES*2];   // per-tile (sum, sumsq)
__device__ float g_stats[NL*NB*NCH*2];         // (mean, rstd)

// ---------------------------------------------------------------------------
// Fused conv kernel.
// PASS==1:  dZ = conv2d(Z, K, pad=1);  also emit per-tile (sum,sumsq) partials
// PASS==2:  Y  = -conv2d( lrelu(inorm(dZ)), Kt, pad=1 ) (+X on l=7, +X0 on l=0)
//           where Kt[o][i][ky][kx] = K[i][o][2-ky][2-kx]
// Block: 256 threads; tile 16x8 spatial, all 64 cout; thread = 4 cout x 8 x.
// ---------------------------------------------------------------------------
template<int PASS>
__global__ __launch_bounds__(256, 2)
void conv_kernel(const float* __restrict__ Kw,
                 const float* __restrict__ X,
                 const float* __restrict__ X0)
{
    __shared__ float sIn[CB*180];    // [cin][10 rows][18 cols]
    __shared__ float sWt[CB*576];    // [cin][64 cout][9]
    __shared__ float sStat[128];     // pass2: (mean,rstd) per cin
    __shared__ float sRed[2048];     // pass1: [64 cout][16 slots][2]

    const int tile = blockIdx.x;
    const int b    = blockIdx.y;
    const int l    = blockIdx.z;
    const int tx   = tile % 6;       // 6 tiles of width 16
    const int ty   = tile / 6;       // 12 tiles of height 8
    const int x0t  = tx * 16;
    const int y0t  = ty * 8;

    const int tid = threadIdx.x;
    const int xg  = tid & 1;         // 0/1: which 8-wide half
    const int yy  = (tid >> 1) & 7;  // row within tile
    const int cg  = tid >> 4;        // cout group (0..15), 4 couts each

    const float* inBase = (PASS == 1 ? g_Z : g_dZ) + (l*NB + b)*IMG;
    const float* kBase  = Kw + l*NCH*NCH*9;

    if (PASS == 2) {
        if (tid < 128) sStat[tid] = g_stats[(l*NB + b)*128 + tid];
    }

    float acc[4][8];
#pragma unroll
    for (int j = 0; j < 4; j++)
#pragma unroll
        for (int xi = 0; xi < 8; xi++) acc[j][xi] = 0.f;

    for (int c0 = 0; c0 < NCH; c0 += CB) {
        __syncthreads();
        // ---- stage input halo tiles (apply inorm+lrelu on pass 2) ----
        for (int i = tid; i < CB*180; i += 256) {
            int ci  = i / 180;
            int rem = i - ci*180;
            int r   = rem / 18;
            int cc  = rem - r*18;
            int gy  = y0t + r - 1;
            int gx  = x0t + cc - 1;
            float v = 0.f;
            if ((unsigned)gy < (unsigned)HH && (unsigned)gx < (unsigned)WW) {
                v = inBase[(c0 + ci)*PLANE + gy*WW + gx];
                if (PASS == 2) {
                    float m  = sStat[(c0 + ci)*2 + 0];
                    float rs = sStat[(c0 + ci)*2 + 1];
                    v = (v - m) * rs;
                    v = (v >= 0.f) ? v : 0.2f * v;
                }
            }
            sIn[i] = v;
        }
        // ---- stage weights ----
        for (int i = tid; i < CB*576; i += 256) {
            int ci  = i / 576;
            int rem = i - ci*576;
            int co  = rem / 9;
            int k   = rem - co*9;
            int gci = c0 + ci;
            float wv;
            if (PASS == 1) wv = kBase[(co*NCH + gci)*9 + k];
            else           wv = kBase[(gci*NCH + co)*9 + (8 - k)];
            sWt[i] = wv;
        }
        __syncthreads();

        // ---- compute ----
#pragma unroll
        for (int ci = 0; ci < CB; ci++) {
            float inr[3][10];
            const float* sp = &sIn[ci*180 + yy*18 + xg*8];
#pragma unroll
            for (int r = 0; r < 3; r++)
#pragma unroll
                for (int cc = 0; cc < 10; cc++)
                    inr[r][cc] = sp[r*18 + cc];

            const float* wrow = &sWt[ci*576 + cg*36];
#pragma unroll
            for (int j = 0; j < 4; j++) {
                const float* wp = wrow + j*9;
                float w0=wp[0],w1=wp[1],w2=wp[2],w3=wp[3],w4=wp[4],
                      w5=wp[5],w6=wp[6],w7=wp[7],w8=wp[8];
#pragma unroll
                for (int xi = 0; xi < 8; xi++) {
                    float s = acc[j][xi];
                    s = fmaf(w0, inr[0][xi  ], s);
                    s = fmaf(w1, inr[0][xi+1], s);
                    s = fmaf(w2, inr[0][xi+2], s);
                    s = fmaf(w3, inr[1][xi  ], s);
                    s = fmaf(w4, inr[1][xi+1], s);
                    s = fmaf(w5, inr[1][xi+2], s);
                    s = fmaf(w6, inr[2][xi  ], s);
                    s = fmaf(w7, inr[2][xi+1], s);
                    s = fmaf(w8, inr[2][xi+2], s);
                    acc[j][xi] = s;
                }
            }
        }
    }

    // ---- epilogue ----
    const int yrow = y0t + yy;
    const int xb   = x0t + xg*8;
    float* outBase = (PASS == 1 ? g_dZ : g_Y) + (l*NB + b)*IMG;

#pragma unroll
    for (int j = 0; j < 4; j++) {
        int co = cg*4 + j;
        float* op = outBase + co*PLANE + yrow*WW + xb;
        if (PASS == 1) {
            float s = 0.f, s2 = 0.f;
#pragma unroll
            for (int xi = 0; xi < 8; xi++) {
                float v = acc[j][xi];
                op[xi] = v;
                s  += v;
                s2 = fmaf(v, v, s2);
            }
            int slot = yy*2 + xg;                 // 0..15
            sRed[(co*16 + slot)*2 + 0] = s;
            sRed[(co*16 + slot)*2 + 1] = s2;
        } else {
            const float* xp  = X  + b*IMG + co*PLANE + yrow*WW + xb;
            const float* x0p = X0 +          co*PLANE + yrow*WW + xb;
#pragma unroll
            for (int xi = 0; xi < 8; xi++) {
                float v = -acc[j][xi];
                if (l == NL-1) v += xp[xi];
                if (l == 0)    v += x0p[xi];
                op[xi] = v;
            }
        }
    }

    if (PASS == 1) {
        __syncthreads();
        if (tid < 64) {                            // deterministic 16-way sum
            float s = 0.f, s2 = 0.f;
#pragma unroll
            for (int t = 0; t < 16; t++) {
                s  += sRed[(tid*16 + t)*2 + 0];
                s2 += sRed[(tid*16 + t)*2 + 1];
            }
            int base = (((l*NB + b)*NCH + tid)*NTILES + tile)*2;
            g_sbuf[base + 0] = s;
            g_sbuf[base + 1] = s2;
        }
    }
}

// ---- instance-norm stats: sum 72 per-tile partials in fixed order ----
__global__ void finalize_kernel()
{
    int i = blockIdx.x*256 + threadIdx.x;          // 0..4095 = (l,b,c)
    if (i >= NL*NB*NCH) return;
    double s = 0.0, s2 = 0.0;
    for (int t = 0; t < NTILES; t++) {
        s  += (double)g_sbuf[(i*NTILES + t)*2 + 0];
        s2 += (double)g_sbuf[(i*NTILES + t)*2 + 1];
    }
    double mean = s  / (double)PLANE;
    double var  = s2 / (double)PLANE - mean*mean;
    if (var < 0.0) var = 0.0;
    g_stats[i*2 + 0] = (float)mean;
    g_stats[i*2 + 1] = rsqrtf((float)var + 1e-5f);
}

// ---- fix-iteration 0 shortcut: Y = [X0, 0,...,0, X] ----
__global__ void buildY0_kernel(const float* __restrict__ X,
                               const float* __restrict__ X0)
{
    int i = blockIdx.x*256 + threadIdx.x;
    if (i >= S4) return;
    float4* Y4 = reinterpret_cast<float4*>(g_Y);
    const float4 z4 = make_float4(0.f, 0.f, 0.f, 0.f);
    Y4[0*S4 + i] = reinterpret_cast<const float4*>(X0)[i % (IMG/4)];
#pragma unroll
    for (int l = 1; l < NL-1; l++) Y4[l*S4 + i] = z4;
    Y4[(NL-1)*S4 + i] = reinterpret_cast<const float4*>(X)[i];
}

// ---- tridiagonal solve: forward + backward first-order recurrences ----
__global__ void scan_kernel()
{
    int i = blockIdx.x*256 + threadIdx.x;
    if (i >= S4) return;
    const float4* Y4 = reinterpret_cast<const float4*>(g_Y);
    float4* Z4 = reinterpret_cast<float4*>(g_Z);

    float4 yf[NL];
    float cx = 0.f, cy = 0.f, cz = 0.f, cw = 0.f;
#pragma unroll
    for (int l = 0; l < NL; l++) {
        float a  = sqrtf((float)(l + 1) / (float)(l + 2));
        float bb = sqrtf((float)l / (float)(l + 1));
        float4 y = Y4[l*S4 + i];
        cx = a * fmaf(bb, cx, y.x);
        cy = a * fmaf(bb, cy, y.y);
        cz = a * fmaf(bb, cz, y.z);
        cw = a * fmaf(bb, cw, y.w);
        yf[l] = make_float4(cx, cy, cz, cw);
    }
    cx = cy = cz = cw = 0.f;
#pragma unroll
    for (int l = NL-1; l >= 0; l--) {
        float a = sqrtf((float)(l + 1) / (float)(l + 2));
        cx = a * fmaf(a, cx, yf[l].x);
        cy = a * fmaf(a, cy, yf[l].y);
        cz = a * fmaf(a, cz, yf[l].z);
        cw = a * fmaf(a, cw, yf[l].w);
        Z4[l*S4 + i] = make_float4(cx, cy, cz, cw);
    }
}

// ---- output: (Z[-1], Z) concatenated (handles out_size = S or 9S) ----
__global__ void write_out_kernel(float* __restrict__ out, int out_size)
{
    int i = blockIdx.x*256 + threadIdx.x;
    if (i >= out_size) return;
    if (out_size > SS) {
        out[i] = (i < SS) ? g_Z[(NL-1)*SS + i] : g_Z[i - SS];
    } else {
        out[i] = g_Z[(NL-1)*SS + i];
    }
}

// ---------------------------------------------------------------------------
extern "C" void kernel_launch(void* const* d_in, const int* in_sizes, int n_in,
                              void* d_out, int out_size)
{
    const float* X  = (const float*)d_in[0];   // [8,64,96,96]
    const float* Kw = (const float*)d_in[1];   // [8,64,64,3,3]
    const float* X0 = (const float*)d_in[2];   // [1,64,96,96]
    float* out = (float*)d_out;

    dim3 cgrid(NTILES, NB, NL);
    const int eb = S4 / 256;                    // 4608 blocks, exact

    // fix iteration 0: Z starts at zero -> layer output is exactly zero
    buildY0_kernel<<<eb, 256>>>(X, X0);
    scan_kernel<<<eb, 256>>>();

    // fix iterations 1..3
    for (int f = 1; f < 4; f++) {
        conv_kernel<1><<<cgrid, 256>>>(Kw, X, X0);
        finalize_kernel<<<16, 256>>>();
        conv_kernel<2><<<cgrid, 256>>>(Kw, X, X0);
        scan_kernel<<<eb, 256>>>();
    }

    write_out_kernel<<<(out_size + 255)/256, 256>>>(out, out_size);
}

// round 15
// speedup vs baseline: 1.0009x; 1.0009x over previous
#include <cuda_runtime.h>
#include <math.h>

// ---------------- problem constants ----------------
#define NL     8          // layers
#define NB     8          // batch
#define NCH    64         // channels
#define HH     96
#define WW     96
#define PLANE  (HH*WW)            // 9216
#define IMG    (NCH*PLANE)        // 589824
#define SS     (NB*IMG)           // 4718592  (one layer-slot: [B,C,H,W])
#define S4     (SS/4)             // 1179648
#define NTILES 72                 // (96/16) * (96/8)
#define CB     8                  // cin chunk

// ---------------- scratch (device globals; no mallocs allowed) ----------------
__device__ float g_Z [NL*SS];     // ~151 MB
__device__ float g_dZ[NL*SS];     // ~151 MB
__device__ float g_Y [NL*SS];     // ~151 MB
__device__ float g_sbuf[NL*NB*NCH*NTILES*2];   // per-tile (sum, sumsq)
__device__ float g_stats[NL*NB*NCH*2];         // (mean, rstd)

// ---------------------------------------------------------------------------
// Fused conv kernel.
// PASS==1:  dZ = conv2d(Z, K, pad=1);  also emit per-tile (sum,sumsq) partials
// PASS==2:  Y  = -conv2d( lrelu(inorm(dZ)), Kt, pad=1 ) (+X on l=7, +X0 on l=0)
//           where Kt[o][i][ky][kx] = K[i][o][2-ky][2-kx]
// Block: 256 threads; tile 16x8 spatial, all 64 cout; thread = 4 cout x 8 x.
// ---------------------------------------------------------------------------
template<int PASS>
__global__ __launch_bounds__(256, 2)
void conv_kernel(const float* __restrict__ Kw,
                 const float* __restrict__ X,
                 const float* __restrict__ X0)
{
    __shared__ float sIn[CB*180];    // [cin][10 rows][18 cols]
    __shared__ float sWt[CB*576];    // [cin][64 cout][9]
    __shared__ float sStat[128];     // pass2: (mean,rstd) per cin
    __shared__ float sRed[2048];     // pass1: [64 cout][16 slots][2]

    const int tile = blockIdx.x;
    const int b    = blockIdx.y;
    const int l    = blockIdx.z;
    const int tx   = tile % 6;       // 6 tiles of width 16
    const int ty   = tile / 6;       // 12 tiles of height 8
    const int x0t  = tx * 16;
    const int y0t  = ty * 8;

    const int tid = threadIdx.x;
    const int xg  = tid & 1;         // 0/1: which 8-wide half
    const int yy  = (tid >> 1) & 7;  // row within tile
    const int cg  = tid >> 4;        // cout group (0..15), 4 couts each

    const float* inBase = (PASS == 1 ? g_Z : g_dZ) + (l*NB + b)*IMG;
    const float* kBase  = Kw + l*NCH*NCH*9;

    if (PASS == 2) {
        if (tid < 128) sStat[tid] = g_stats[(l*NB + b)*128 + tid];
    }

    float acc[4][8];
#pragma unroll
    for (int j = 0; j < 4; j++)
#pragma unroll
        for (int xi = 0; xi < 8; xi++) acc[j][xi] = 0.f;

    for (int c0 = 0; c0 < NCH; c0 += CB) {
        __syncthreads();
        // ---- stage input halo tiles (apply inorm+lrelu on pass 2) ----
        for (int i = tid; i < CB*180; i += 256) {
            int ci  = i / 180;
            int rem = i - ci*180;
            int r   = rem / 18;
            int cc  = rem - r*18;
            int gy  = y0t + r - 1;
            int gx  = x0t + cc - 1;
            float v = 0.f;
            if ((unsigned)gy < (unsigned)HH && (unsigned)gx < (unsigned)WW) {
                v = inBase[(c0 + ci)*PLANE + gy*WW + gx];
                if (PASS == 2) {
                    float m  = sStat[(c0 + ci)*2 + 0];
                    float rs = sStat[(c0 + ci)*2 + 1];
                    v = (v - m) * rs;
                    v = (v >= 0.f) ? v : 0.2f * v;
                }
            }
            sIn[i] = v;
        }
        // ---- stage weights ----
        for (int i = tid; i < CB*576; i += 256) {
            int ci  = i / 576;
            int rem = i - ci*576;
            int co  = rem / 9;
            int k   = rem - co*9;
            int gci = c0 + ci;
            float wv;
            if (PASS == 1) wv = kBase[(co*NCH + gci)*9 + k];
            else           wv = kBase[(gci*NCH + co)*9 + (8 - k)];
            sWt[i] = wv;
        }
        __syncthreads();

        // ---- compute ----
#pragma unroll
        for (int ci = 0; ci < CB; ci++) {
            float inr[3][10];
            const float* sp = &sIn[ci*180 + yy*18 + xg*8];
#pragma unroll
            for (int r = 0; r < 3; r++)
#pragma unroll
                for (int cc = 0; cc < 10; cc++)
                    inr[r][cc] = sp[r*18 + cc];

            const float* wrow = &sWt[ci*576 + cg*36];
#pragma unroll
            for (int j = 0; j < 4; j++) {
                const float* wp = wrow + j*9;
                float w0=wp[0],w1=wp[1],w2=wp[2],w3=wp[3],w4=wp[4],
                      w5=wp[5],w6=wp[6],w7=wp[7],w8=wp[8];
#pragma unroll
                for (int xi = 0; xi < 8; xi++) {
                    float s = acc[j][xi];
                    s = fmaf(w0, inr[0][xi  ], s);
                    s = fmaf(w1, inr[0][xi+1], s);
                    s = fmaf(w2, inr[0][xi+2], s);
                    s = fmaf(w3, inr[1][xi  ], s);
                    s = fmaf(w4, inr[1][xi+1], s);
                    s = fmaf(w5, inr[1][xi+2], s);
                    s = fmaf(w6, inr[2][xi  ], s);
                    s = fmaf(w7, inr[2][xi+1], s);
                    s = fmaf(w8, inr[2][xi+2], s);
                    acc[j][xi] = s;
                }
            }
        }
    }

    // ---- epilogue ----
    const int yrow = y0t + yy;
    const int xb   = x0t + xg*8;
    float* outBase = (PASS == 1 ? g_dZ : g_Y) + (l*NB + b)*IMG;

#pragma unroll
    for (int j = 0; j < 4; j++) {
        int co = cg*4 + j;
        float* op = outBase + co*PLANE + yrow*WW + xb;
        if (PASS == 1) {
            float s = 0.f, s2 = 0.f;
#pragma unroll
            for (int xi = 0; xi < 8; xi++) {
                float v = acc[j][xi];
                op[xi] = v;
                s  += v;
                s2 = fmaf(v, v, s2);
            }
            int slot = yy*2 + xg;                 // 0..15
            sRed[(co*16 + slot)*2 + 0] = s;
            sRed[(co*16 + slot)*2 + 1] = s2;
        } else {
            const float* xp  = X  + b*IMG + co*PLANE + yrow*WW + xb;
            const float* x0p = X0 +          co*PLANE + yrow*WW + xb;
#pragma unroll
            for (int xi = 0; xi < 8; xi++) {
                float v = -acc[j][xi];
                if (l == NL-1) v += xp[xi];
                if (l == 0)    v += x0p[xi];
                op[xi] = v;
            }
        }
    }

    if (PASS == 1) {
        __syncthreads();
        if (tid < 64) {                            // deterministic 16-way sum
            float s = 0.f, s2 = 0.f;
#pragma unroll
            for (int t = 0; t < 16; t++) {
                s  += sRed[(tid*16 + t)*2 + 0];
                s2 += sRed[(tid*16 + t)*2 + 1];
            }
            int base = (((l*NB + b)*NCH + tid)*NTILES + tile)*2;
            g_sbuf[base + 0] = s;
            g_sbuf[base + 1] = s2;
        }
    }
}

// ---- instance-norm stats: sum 72 per-tile partials in fixed order ----
__global__ void finalize_kernel()
{
    int i = blockIdx.x*256 + threadIdx.x;          // 0..4095 = (l,b,c)
    if (i >= NL*NB*NCH) return;
    double s = 0.0, s2 = 0.0;
    for (int t = 0; t < NTILES; t++) {
        s  += (double)g_sbuf[(i*NTILES + t)*2 + 0];
        s2 += (double)g_sbuf[(i*NTILES + t)*2 + 1];
    }
    double mean = s  / (double)PLANE;
    double var  = s2 / (double)PLANE - mean*mean;
    if (var < 0.0) var = 0.0;
    g_stats[i*2 + 0] = (float)mean;
    g_stats[i*2 + 1] = rsqrtf((float)var + 1e-5f);
}

// ---- fix-iteration 0 shortcut: Y = [X0, 0,...,0, X] ----
__global__ void buildY0_kernel(const float* __restrict__ X,
                               const float* __restrict__ X0)
{
    int i = blockIdx.x*256 + threadIdx.x;
    if (i >= S4) return;
    float4* Y4 = reinterpret_cast<float4*>(g_Y);
    const float4 z4 = make_float4(0.f, 0.f, 0.f, 0.f);
    Y4[0*S4 + i] = reinterpret_cast<const float4*>(X0)[i % (IMG/4)];
#pragma unroll
    for (int l = 1; l < NL-1; l++) Y4[l*S4 + i] = z4;
    Y4[(NL-1)*S4 + i] = reinterpret_cast<const float4*>(X)[i];
}

// ---- tridiagonal solve: forward + backward first-order recurrences ----
__global__ void scan_kernel()
{
    int i = blockIdx.x*256 + threadIdx.x;
    if (i >= S4) return;
    const float4* Y4 = reinterpret_cast<const float4*>(g_Y);
    float4* Z4 = reinterpret_cast<float4*>(g_Z);

    float4 yf[NL];
    float cx = 0.f, cy = 0.f, cz = 0.f, cw = 0.f;
#pragma unroll
    for (int l = 0; l < NL; l++) {
        float a  = sqrtf((float)(l + 1) / (float)(l + 2));
        float bb = sqrtf((float)l / (float)(l + 1));
        float4 y = Y4[l*S4 + i];
        cx = a * fmaf(bb, cx, y.x);
        cy = a * fmaf(bb, cy, y.y);
        cz = a * fmaf(bb, cz, y.z);
        cw = a * fmaf(bb, cw, y.w);
        yf[l] = make_float4(cx, cy, cz, cw);
    }
    cx = cy = cz = cw = 0.f;
#pragma unroll
    for (int l = NL-1; l >= 0; l--) {
        float a = sqrtf((float)(l + 1) / (float)(l + 2));
        cx = a * fmaf(a, cx, yf[l].x);
        cy = a * fmaf(a, cy, yf[l].y);
        cz = a * fmaf(a, cz, yf[l].z);
        cw = a * fmaf(a, cw, yf[l].w);
        Z4[l*S4 + i] = make_float4(cx, cy, cz, cw);
    }
}

// ---- output: (Z[-1], Z) concatenated (handles out_size = S or 9S) ----
__global__ void write_out_kernel(float* __restrict__ out, int out_size)
{
    int i = blockIdx.x*256 + threadIdx.x;
    if (i >= out_size) return;
    if (out_size > SS) {
        out[i] = (i < SS) ? g_Z[(NL-1)*SS + i] : g_Z[i - SS];
    } else {
        out[i] = g_Z[(NL-1)*SS + i];
    }
}

// ---------------------------------------------------------------------------
extern "C" void kernel_launch(void* const* d_in, const int* in_sizes, int n_in,
                              void* d_out, int out_size)
{
    const float* X  = (const float*)d_in[0];   // [8,64,96,96]
    const float* Kw = (const float*)d_in[1];   // [8,64,64,3,3]
    const float* X0 = (const float*)d_in[2];   // [1,64,96,96]
    float* out = (float*)d_out;

    dim3 cgrid(NTILES, NB, NL);
    const int eb = S4 / 256;                    // 4608 blocks, exact

    // fix iteration 0: Z starts at zero -> layer output is exactly zero
    buildY0_kernel<<<eb, 256>>>(X, X0);
    scan_kernel<<<eb, 256>>>();

    // fix iterations 1..3
    for (int f = 1; f < 4; f++) {
        conv_kernel<1><<<cgrid, 256>>>(Kw, X, X0);
        finalize_kernel<<<16, 256>>>();
        conv_kernel<2><<<cgrid, 256>>>(Kw, X, X0);
        scan_kernel<<<eb, 256>>>();
    }

    write_out_kernel<<<(out_size + 255)/256, 256>>>(out, out_size);
}